// round 1
// baseline (speedup 1.0000x reference)
#include <cuda_runtime.h>
#include <cstdint>

// Problem constants
#define BATCH 2
#define SEQN  8192
#define DMODEL 512
#define HEADS 8
#define DK 64
#define KNN 32
#define MROWS (BATCH*SEQN)   // 16384
#define LN_EPS 1e-5f

// ---------------- scratch (device globals; no allocation allowed) -------------
__device__ float g_Q[MROWS * DMODEL];
__device__ float g_K[MROWS * DMODEL];
__device__ float g_V[MROWS * DMODEL];
__device__ float g_att[MROWS * DMODEL];

// ---------------- warp reduce helpers -----------------------------------------
__device__ __forceinline__ float warp_sum(float v) {
    v += __shfl_xor_sync(0xffffffffu, v, 16);
    v += __shfl_xor_sync(0xffffffffu, v, 8);
    v += __shfl_xor_sync(0xffffffffu, v, 4);
    v += __shfl_xor_sync(0xffffffffu, v, 2);
    v += __shfl_xor_sync(0xffffffffu, v, 1);
    return v;
}
__device__ __forceinline__ float warp_max(float v) {
    v = fmaxf(v, __shfl_xor_sync(0xffffffffu, v, 16));
    v = fmaxf(v, __shfl_xor_sync(0xffffffffu, v, 8));
    v = fmaxf(v, __shfl_xor_sync(0xffffffffu, v, 4));
    v = fmaxf(v, __shfl_xor_sync(0xffffffffu, v, 2));
    v = fmaxf(v, __shfl_xor_sync(0xffffffffu, v, 1));
    return v;
}

// ---------------- SGEMM: C = A (MxK) * B^T (B is NxK row-major) ---------------
// A: Mdim x 512 row-major, Bmat: 512 x 512 row-major, C: Mdim x 512 row-major.
// Tile 128x128, BK=8, 256 threads, 8x8 per thread.
#define BM 128
#define BN 128
#define BKK 8
#define TM 8
#define TN 8

__global__ __launch_bounds__(256, 2)
void sgemm_nt(const float* __restrict__ A, const float* __restrict__ Bmat,
              float* __restrict__ C, const float* __restrict__ bias)
{
    __shared__ float As[BKK][BM];
    __shared__ float Bs[BKK][BN];

    const int tid = threadIdx.x;
    const int bm = blockIdx.y * BM;
    const int bn = blockIdx.x * BN;
    const int tx = tid & 15;        // 0..15 -> columns
    const int ty = tid >> 4;        // 0..15 -> rows

    const int lrow = tid >> 1;          // 0..127
    const int lk4  = (tid & 1) * 4;     // 0 or 4

    const float* Aptr = A + (bm + lrow) * DMODEL + lk4;
    const float* Bptr = Bmat + (bn + lrow) * DMODEL + lk4;

    float acc[TM][TN];
    #pragma unroll
    for (int i = 0; i < TM; i++)
        #pragma unroll
        for (int j = 0; j < TN; j++) acc[i][j] = 0.f;

    for (int k0 = 0; k0 < DMODEL; k0 += BKK) {
        float4 av = *(const float4*)(Aptr + k0);
        float4 bv = *(const float4*)(Bptr + k0);
        As[lk4 + 0][lrow] = av.x; As[lk4 + 1][lrow] = av.y;
        As[lk4 + 2][lrow] = av.z; As[lk4 + 3][lrow] = av.w;
        Bs[lk4 + 0][lrow] = bv.x; Bs[lk4 + 1][lrow] = bv.y;
        Bs[lk4 + 2][lrow] = bv.z; Bs[lk4 + 3][lrow] = bv.w;
        __syncthreads();

        #pragma unroll
        for (int kk = 0; kk < BKK; kk++) {
            float a[TM], b[TN];
            #pragma unroll
            for (int i = 0; i < TM; i += 4) {
                float4 t = *(const float4*)&As[kk][ty * TM + i];
                a[i] = t.x; a[i+1] = t.y; a[i+2] = t.z; a[i+3] = t.w;
            }
            #pragma unroll
            for (int j = 0; j < TN; j += 4) {
                float4 t = *(const float4*)&Bs[kk][tx * TN + j];
                b[j] = t.x; b[j+1] = t.y; b[j+2] = t.z; b[j+3] = t.w;
            }
            #pragma unroll
            for (int i = 0; i < TM; i++)
                #pragma unroll
                for (int j = 0; j < TN; j++)
                    acc[i][j] = fmaf(a[i], b[j], acc[i][j]);
        }
        __syncthreads();
    }

    // epilogue
    #pragma unroll
    for (int i = 0; i < TM; i++) {
        int row = bm + ty * TM + i;
        int col = bn + tx * TN;
        if (bias != nullptr) {
            #pragma unroll
            for (int j = 0; j < TN; j++) acc[i][j] += bias[col + j];
        }
        float4 v0 = make_float4(acc[i][0], acc[i][1], acc[i][2], acc[i][3]);
        float4 v1 = make_float4(acc[i][4], acc[i][5], acc[i][6], acc[i][7]);
        *(float4*)(C + row * DMODEL + col)     = v0;
        *(float4*)(C + row * DMODEL + col + 4) = v1;
    }
}

// ---------------- LayerNorm over 64-element groups (in place) -----------------
// Tensors Q and K: MROWS*HEADS groups each, group = 64 contiguous floats.
__global__ void ln64_kernel(float* __restrict__ Q, float* __restrict__ Kt)
{
    const int warps_per_block = blockDim.x >> 5;
    int gid = blockIdx.x * warps_per_block + (threadIdx.x >> 5);
    const int lane = threadIdx.x & 31;
    const int total = MROWS * HEADS;      // groups per tensor
    float* base;
    if (gid < total) base = Q + (size_t)gid * DK;
    else             base = Kt + (size_t)(gid - total) * DK;

    float v0 = base[lane];
    float v1 = base[lane + 32];
    float mean = warp_sum(v0 + v1) * (1.0f / 64.0f);
    float d0 = v0 - mean, d1 = v1 - mean;
    float var = warp_sum(d0 * d0 + d1 * d1) * (1.0f / 64.0f);
    float r = rsqrtf(var + LN_EPS);
    base[lane]      = d0 * r;
    base[lane + 32] = d1 * r;
}

// ---------------- fused gather-attention ---------------------------------------
// One block per (b, n); 8 warps = 8 heads; lane plays "key index" in phase 1
// and "dim index" in phase 2.
__global__ __launch_bounds__(256)
void attn_kernel(const float* __restrict__ Q, const float* __restrict__ Kt,
                 const float* __restrict__ V, const int* __restrict__ idx,
                 float* __restrict__ att)
{
    __shared__ int srows[KNN];
    const int bn = blockIdx.x;          // 0 .. MROWS-1
    const int b  = bn >> 13;            // / 8192
    const int n  = bn & (SEQN - 1);
    const int tid = threadIdx.x;
    if (tid < KNN) srows[tid] = idx[n * KNN + tid];
    __syncthreads();

    const int h    = tid >> 5;
    const int lane = tid & 31;
    const int qbase = bn * DMODEL + h * DK;
    const float q0 = Q[qbase + lane];
    const float q1 = Q[qbase + 32 + lane];
    const int rowbase = b * SEQN;       // add row, then *512 + h*64

    // phase 1: scores; lane ends holding score for key == lane
    float s = 0.f;
    #pragma unroll 4
    for (int k = 0; k < KNN; ++k) {
        const int row = srows[k];
        const float* kp = Kt + (rowbase + row) * DMODEL + h * DK;
        float p = fmaf(q0, kp[lane], q1 * kp[lane + 32]);
        p += __shfl_xor_sync(0xffffffffu, p, 16);
        p += __shfl_xor_sync(0xffffffffu, p, 8);
        p += __shfl_xor_sync(0xffffffffu, p, 4);
        p += __shfl_xor_sync(0xffffffffu, p, 2);
        p += __shfl_xor_sync(0xffffffffu, p, 1);
        if (lane == k) s = p;
    }
    s *= 0.125f;  // 1/sqrt(64)

    // softmax across the 32 lanes (= 32 keys)
    const float m = warp_max(s);
    const float e = __expf(s - m);
    const float denom = warp_sum(e);
    const float a = e / denom;

    // phase 2: out[d] = sum_k a_k * V[row_k, d]; lane covers d = lane, lane+32
    float o0 = 0.f, o1 = 0.f;
    #pragma unroll 4
    for (int k = 0; k < KNN; ++k) {
        const int row = srows[k];
        const float ak = __shfl_sync(0xffffffffu, a, k);
        const float* vp = V + (rowbase + row) * DMODEL + h * DK;
        o0 = fmaf(ak, vp[lane],      o0);
        o1 = fmaf(ak, vp[lane + 32], o1);
    }
    att[qbase + lane]      = o0;
    att[qbase + 32 + lane] = o1;
}

// ---------------- launch ---------------------------------------------------------
extern "C" void kernel_launch(void* const* d_in, const int* in_sizes, int n_in,
                              void* d_out, int out_size)
{
    const float* x    = (const float*)d_in[0];
    const int*   idx  = (const int*)  d_in[1];
    const float* Wq   = (const float*)d_in[2];
    const float* Wk   = (const float*)d_in[3];
    const float* Wv   = (const float*)d_in[4];
    const float* Wout = (const float*)d_in[5];
    const float* bout = (const float*)d_in[6];
    float* out = (float*)d_out;

    static float *gQ = nullptr, *gK = nullptr, *gV = nullptr, *gA = nullptr;
    if (!gQ) {
        cudaGetSymbolAddress((void**)&gQ, g_Q);
        cudaGetSymbolAddress((void**)&gK, g_K);
        cudaGetSymbolAddress((void**)&gV, g_V);
        cudaGetSymbolAddress((void**)&gA, g_att);
    }

    dim3 gblock(256);
    dim3 ggrid(DMODEL / BN, MROWS / BM);   // (4, 128)

    // 1) projections (natural layout: row m = b*N+n, col j = h*64+d)
    sgemm_nt<<<ggrid, gblock>>>(x, Wq, gQ, nullptr);
    sgemm_nt<<<ggrid, gblock>>>(x, Wk, gK, nullptr);
    sgemm_nt<<<ggrid, gblock>>>(x, Wv, gV, nullptr);

    // 2) LayerNorm on Q and K (per 64-dim head group)
    {
        int total_groups = 2 * MROWS * HEADS;      // both tensors
        int warps_per_block = 8;
        int blocks = total_groups / warps_per_block;
        ln64_kernel<<<blocks, 256>>>(gQ, gK);
    }

    // 3) gather attention
    attn_kernel<<<MROWS, 256>>>(gQ, gK, gV, idx, gA);

    // 4) output projection + bias -> d_out
    sgemm_nt<<<ggrid, gblock>>>(gA, Wout, out, bout);
}

// round 3
// speedup vs baseline: 1.8568x; 1.8568x over previous
#include <cuda_runtime.h>
#include <cuda_bf16.h>
#include <cstdint>

// Problem constants
#define BATCH 2
#define SEQN  8192
#define DMODEL 512
#define HEADS 8
#define DK 64
#define KNN 32
#define MROWS (BATCH*SEQN)   // 16384
#define LN_EPS 1e-5f

// ---------------- scratch (device globals; no allocation allowed) -------------
__device__ __align__(128) float g_Q[MROWS * DMODEL];
__device__ __align__(128) float g_K[MROWS * DMODEL];
__device__ __align__(128) float g_V[MROWS * DMODEL];
__device__ __align__(128) __nv_bfloat16 g_xh[MROWS * DMODEL];
__device__ __align__(128) __nv_bfloat16 g_xl[MROWS * DMODEL];
__device__ __align__(128) __nv_bfloat16 g_ah[MROWS * DMODEL];
__device__ __align__(128) __nv_bfloat16 g_al[MROWS * DMODEL];
__device__ __align__(128) __nv_bfloat16 g_Wh[4 * DMODEL * DMODEL];
__device__ __align__(128) __nv_bfloat16 g_Wl[4 * DMODEL * DMODEL];

// ---------------- small helpers -------------------------------------------------
__device__ __forceinline__ uint32_t smem_u32(const void* p) {
    uint32_t a;
    asm("{ .reg .u64 t; cvta.to.shared.u64 t, %1; cvt.u32.u64 %0, t; }"
        : "=r"(a) : "l"(p));
    return a;
}

__device__ __forceinline__ void ldsm_x4(uint32_t (&r)[4], uint32_t addr) {
    asm volatile("ldmatrix.sync.aligned.m8n8.x4.shared.b16 {%0,%1,%2,%3}, [%4];"
                 : "=r"(r[0]), "=r"(r[1]), "=r"(r[2]), "=r"(r[3]) : "r"(addr));
}

__device__ __forceinline__ void mma16816(float (&c)[4], const uint32_t (&a)[4],
                                         const uint32_t b0, const uint32_t b1) {
    asm volatile("mma.sync.aligned.m16n8k16.row.col.f32.bf16.bf16.f32 "
                 "{%0,%1,%2,%3}, {%4,%5,%6,%7}, {%8,%9}, {%0,%1,%2,%3};"
                 : "+f"(c[0]), "+f"(c[1]), "+f"(c[2]), "+f"(c[3])
                 : "r"(a[0]), "r"(a[1]), "r"(a[2]), "r"(a[3]), "r"(b0), "r"(b1));
}

__device__ __forceinline__ void cp16(uint32_t saddr, const void* gaddr) {
    asm volatile("cp.async.cg.shared.global [%0], [%1], 16;"
                 :: "r"(saddr), "l"(gaddr) : "memory");
}
#define CP_COMMIT() asm volatile("cp.async.commit_group;" ::: "memory")
#define CP_WAIT1()  asm volatile("cp.async.wait_group 1;" ::: "memory")
#define CP_WAIT0()  asm volatile("cp.async.wait_group 0;" ::: "memory")

// ---------------- tensor-core GEMM: C = A(16384x512) * W^T ----------------------
// A, W as bf16 hi/lo splits; fp32 accum via 3 MMAs (hh + hl + lh).
// CTA tile 128x128, BK=32, 8 warps (2x4), warp tile 64x32, 2-stage cp.async.
#define BKC 32
#define NCH (DMODEL / BKC)     // 16
#define PITCH 40               // bf16 elements per smem row (80B, conflict-free ldmatrix)
#define TILE_B (128 * PITCH * 2)        // 10240 B per tile
#define STAGE_B (4 * TILE_B)            // Ah, Al, Bh, Bl
#define GEMM_SMEM (2 * STAGE_B)         // 81920 B

__global__ __launch_bounds__(256, 1)
void gemm_hmma3(const __nv_bfloat16* __restrict__ Ah, const __nv_bfloat16* __restrict__ Al,
                const __nv_bfloat16* __restrict__ Bh, const __nv_bfloat16* __restrict__ Bl,
                float* __restrict__ C, const float* __restrict__ bias)
{
    extern __shared__ char smem[];
    const uint32_t sbase = smem_u32(smem);
    const int tid  = threadIdx.x;
    const int wid  = tid >> 5;
    const int lane = tid & 31;
    const int bm = blockIdx.y * 128;
    const int bn = blockIdx.x * 128;
    const int warp_m = wid & 1;        // 0..1
    const int warp_n = wid >> 1;       // 0..3

    const __nv_bfloat16* gsrc[4] = {Ah, Al, Bh, Bl};

    // loader mapping: per tile, 512 uint4; thread does e = tid, tid+256
    const int lr0 = tid >> 2;            // row 0..63
    const int lc  = tid & 3;             // 16B chunk 0..3

    // issue one stage of cp.async
    auto load_stage = [&](int c, int buf) {
        const uint32_t s0 = sbase + buf * STAGE_B;
        const int kc = c * BKC;
        #pragma unroll
        for (int t = 0; t < 4; ++t) {
            const __nv_bfloat16* g = gsrc[t];
            const int rowbase = (t < 2) ? bm : bn;
            const uint32_t tb = s0 + t * TILE_B;
            #pragma unroll
            for (int p = 0; p < 2; ++p) {
                const int r = lr0 + p * 64;
                cp16(tb + (uint32_t)(r * (PITCH * 2) + lc * 16),
                     g + (size_t)(rowbase + r) * DMODEL + kc + lc * 8);
            }
        }
        CP_COMMIT();
    };

    float acc[4][4][4];
    #pragma unroll
    for (int i = 0; i < 4; i++)
        #pragma unroll
        for (int j = 0; j < 4; j++)
            #pragma unroll
            for (int r = 0; r < 4; r++) acc[i][j][r] = 0.f;

    load_stage(0, 0);
    load_stage(1, 1);

    // ldmatrix lane addressing (element offsets)
    const int aRow  = lane & 15;
    const int aColB = (lane >> 4) * 8;
    const int quad  = lane >> 3;
    const int bRow  = warp_n * 32 + ((quad >> 1) * 8) + (lane & 7);
    const int bColB = (quad & 1) * 8;

    #pragma unroll 1
    for (int c = 0; c < NCH; ++c) {
        const int buf = c & 1;
        if (c + 1 < NCH) CP_WAIT1(); else CP_WAIT0();
        __syncthreads();

        const uint32_t sAh = sbase + buf * STAGE_B;
        const uint32_t sAl = sAh + TILE_B;
        const uint32_t sBh = sAh + 2 * TILE_B;
        const uint32_t sBl = sAh + 3 * TILE_B;

        #pragma unroll
        for (int ks = 0; ks < 2; ++ks) {
            uint32_t af[2][4][4];
            uint32_t bfr[2][4][2];
            #pragma unroll
            for (int i = 0; i < 4; ++i) {
                const uint32_t ao = (uint32_t)((warp_m * 64 + i * 16 + aRow) * PITCH
                                               + ks * 16 + aColB) * 2;
                ldsm_x4(af[0][i], sAh + ao);
                ldsm_x4(af[1][i], sAl + ao);
            }
            #pragma unroll
            for (int p = 0; p < 2; ++p) {
                const uint32_t bo = (uint32_t)((bRow + p * 16) * PITCH
                                               + ks * 16 + bColB) * 2;
                uint32_t r0[4], r1[4];
                ldsm_x4(r0, sBh + bo);
                ldsm_x4(r1, sBl + bo);
                bfr[0][2*p][0] = r0[0]; bfr[0][2*p][1] = r0[1];
                bfr[0][2*p+1][0] = r0[2]; bfr[0][2*p+1][1] = r0[3];
                bfr[1][2*p][0] = r1[0]; bfr[1][2*p][1] = r1[1];
                bfr[1][2*p+1][0] = r1[2]; bfr[1][2*p+1][1] = r1[3];
            }
            #pragma unroll
            for (int i = 0; i < 4; ++i)
                #pragma unroll
                for (int j = 0; j < 4; ++j) {
                    mma16816(acc[i][j], af[0][i], bfr[0][j][0], bfr[0][j][1]);
                    mma16816(acc[i][j], af[0][i], bfr[1][j][0], bfr[1][j][1]);
                    mma16816(acc[i][j], af[1][i], bfr[0][j][0], bfr[0][j][1]);
                }
        }
        __syncthreads();
        if (c + 2 < NCH) load_stage(c + 2, buf);
    }

    // epilogue
    const int mBase = bm + warp_m * 64 + (lane >> 2);
    const int nBase = bn + warp_n * 32 + (lane & 3) * 2;
    #pragma unroll
    for (int i = 0; i < 4; ++i) {
        #pragma unroll
        for (int j = 0; j < 4; ++j) {
            const int row = mBase + i * 16;
            const int col = nBase + j * 8;
            float2 v0 = make_float2(acc[i][j][0], acc[i][j][1]);
            float2 v1 = make_float2(acc[i][j][2], acc[i][j][3]);
            if (bias) {
                const float b0 = bias[col], b1 = bias[col + 1];
                v0.x += b0; v0.y += b1; v1.x += b0; v1.y += b1;
            }
            *(float2*)(C + (size_t)row * DMODEL + col)       = v0;
            *(float2*)(C + (size_t)(row + 8) * DMODEL + col) = v1;
        }
    }
}

// ---------------- fp32 -> bf16 hi/lo split --------------------------------------
__global__ void cvt_hilo(const float* __restrict__ s,
                         __nv_bfloat16* __restrict__ hi, __nv_bfloat16* __restrict__ lo,
                         int n)
{
    int i = (blockIdx.x * blockDim.x + threadIdx.x) * 4;
    if (i >= n) return;
    float4 v = *(const float4*)(s + i);
    __nv_bfloat16 h0 = __float2bfloat16(v.x);
    __nv_bfloat16 h1 = __float2bfloat16(v.y);
    __nv_bfloat16 h2 = __float2bfloat16(v.z);
    __nv_bfloat16 h3 = __float2bfloat16(v.w);
    __nv_bfloat16 l0 = __float2bfloat16(v.x - __bfloat162float(h0));
    __nv_bfloat16 l1 = __float2bfloat16(v.y - __bfloat162float(h1));
    __nv_bfloat16 l2 = __float2bfloat16(v.z - __bfloat162float(h2));
    __nv_bfloat16 l3 = __float2bfloat16(v.w - __bfloat162float(h3));
    __nv_bfloat162* hp = (__nv_bfloat162*)(hi + i);
    __nv_bfloat162* lp = (__nv_bfloat162*)(lo + i);
    hp[0] = __nv_bfloat162{h0, h1}; hp[1] = __nv_bfloat162{h2, h3};
    lp[0] = __nv_bfloat162{l0, l1}; lp[1] = __nv_bfloat162{l2, l3};
}

// ---------------- warp reduce helpers -----------------------------------------
__device__ __forceinline__ float warp_sum(float v) {
    v += __shfl_xor_sync(0xffffffffu, v, 16);
    v += __shfl_xor_sync(0xffffffffu, v, 8);
    v += __shfl_xor_sync(0xffffffffu, v, 4);
    v += __shfl_xor_sync(0xffffffffu, v, 2);
    v += __shfl_xor_sync(0xffffffffu, v, 1);
    return v;
}
__device__ __forceinline__ float warp_max(float v) {
    v = fmaxf(v, __shfl_xor_sync(0xffffffffu, v, 16));
    v = fmaxf(v, __shfl_xor_sync(0xffffffffu, v, 8));
    v = fmaxf(v, __shfl_xor_sync(0xffffffffu, v, 4));
    v = fmaxf(v, __shfl_xor_sync(0xffffffffu, v, 2));
    v = fmaxf(v, __shfl_xor_sync(0xffffffffu, v, 1));
    return v;
}

// ---------------- LayerNorm over 64-element groups (in place) -----------------
__global__ void ln64_kernel(float* __restrict__ Q, float* __restrict__ Kt)
{
    const int warps_per_block = blockDim.x >> 5;
    int gid = blockIdx.x * warps_per_block + (threadIdx.x >> 5);
    const int lane = threadIdx.x & 31;
    const int total = MROWS * HEADS;
    float* base;
    if (gid < total) base = Q + (size_t)gid * DK;
    else             base = Kt + (size_t)(gid - total) * DK;

    float v0 = base[lane];
    float v1 = base[lane + 32];
    float mean = warp_sum(v0 + v1) * (1.0f / 64.0f);
    float d0 = v0 - mean, d1 = v1 - mean;
    float var = warp_sum(d0 * d0 + d1 * d1) * (1.0f / 64.0f);
    float r = rsqrtf(var + LN_EPS);
    base[lane]      = d0 * r;
    base[lane + 32] = d1 * r;
}

// ---------------- fused gather-attention (bf16 hi/lo output) --------------------
__global__ __launch_bounds__(256)
void attn_kernel(const float* __restrict__ Q, const float* __restrict__ Kt,
                 const float* __restrict__ V, const int* __restrict__ idx,
                 __nv_bfloat16* __restrict__ oh, __nv_bfloat16* __restrict__ ol)
{
    __shared__ int srows[KNN];
    const int bn = blockIdx.x;
    const int b  = bn >> 13;
    const int n  = bn & (SEQN - 1);
    const int tid = threadIdx.x;
    if (tid < KNN) srows[tid] = idx[n * KNN + tid];
    __syncthreads();

    const int h    = tid >> 5;
    const int lane = tid & 31;
    const int qbase = bn * DMODEL + h * DK;
    const float q0 = Q[qbase + lane];
    const float q1 = Q[qbase + 32 + lane];
    const int rowbase = b * SEQN;

    float s = 0.f;
    #pragma unroll 4
    for (int k = 0; k < KNN; ++k) {
        const int row = srows[k];
        const float* kp = Kt + (size_t)(rowbase + row) * DMODEL + h * DK;
        float p = fmaf(q0, kp[lane], q1 * kp[lane + 32]);
        p += __shfl_xor_sync(0xffffffffu, p, 16);
        p += __shfl_xor_sync(0xffffffffu, p, 8);
        p += __shfl_xor_sync(0xffffffffu, p, 4);
        p += __shfl_xor_sync(0xffffffffu, p, 2);
        p += __shfl_xor_sync(0xffffffffu, p, 1);
        if (lane == k) s = p;
    }
    s *= 0.125f;

    const float m = warp_max(s);
    const float e = __expf(s - m);
    const float denom = warp_sum(e);
    const float a = e / denom;

    float o0 = 0.f, o1 = 0.f;
    #pragma unroll 4
    for (int k = 0; k < KNN; ++k) {
        const int row = srows[k];
        const float ak = __shfl_sync(0xffffffffu, a, k);
        const float* vp = V + (size_t)(rowbase + row) * DMODEL + h * DK;
        o0 = fmaf(ak, vp[lane],      o0);
        o1 = fmaf(ak, vp[lane + 32], o1);
    }
    __nv_bfloat16 h0 = __float2bfloat16(o0);
    __nv_bfloat16 h1 = __float2bfloat16(o1);
    oh[qbase + lane]      = h0;
    oh[qbase + 32 + lane] = h1;
    ol[qbase + lane]      = __float2bfloat16(o0 - __bfloat162float(h0));
    ol[qbase + 32 + lane] = __float2bfloat16(o1 - __bfloat162float(h1));
}

// ---------------- launch ---------------------------------------------------------
extern "C" void kernel_launch(void* const* d_in, const int* in_sizes, int n_in,
                              void* d_out, int out_size)
{
    const float* x    = (const float*)d_in[0];
    const int*   idx  = (const int*)  d_in[1];
    const float* Wq   = (const float*)d_in[2];
    const float* Wk   = (const float*)d_in[3];
    const float* Wv   = (const float*)d_in[4];
    const float* Wout = (const float*)d_in[5];
    const float* bout = (const float*)d_in[6];
    float* out = (float*)d_out;

    static float *gQ = nullptr, *gK = nullptr, *gV = nullptr;
    static __nv_bfloat16 *xh, *xl, *ah, *al, *wh, *wl;
    if (!gQ) {
        cudaGetSymbolAddress((void**)&gQ, g_Q);
        cudaGetSymbolAddress((void**)&gK, g_K);
        cudaGetSymbolAddress((void**)&gV, g_V);
        cudaGetSymbolAddress((void**)&xh, g_xh);
        cudaGetSymbolAddress((void**)&xl, g_xl);
        cudaGetSymbolAddress((void**)&ah, g_ah);
        cudaGetSymbolAddress((void**)&al, g_al);
        cudaGetSymbolAddress((void**)&wh, g_Wh);
        cudaGetSymbolAddress((void**)&wl, g_Wl);
        cudaFuncSetAttribute(gemm_hmma3, cudaFuncAttributeMaxDynamicSharedMemorySize,
                             GEMM_SMEM);
    }

    const int NX = MROWS * DMODEL;      // 8388608
    const int NW = DMODEL * DMODEL;     // 262144

    cvt_hilo<<<NX / 1024, 256>>>(x, xh, xl, NX);
    cvt_hilo<<<NW / 1024, 256>>>(Wq,   wh + 0 * NW, wl + 0 * NW, NW);
    cvt_hilo<<<NW / 1024, 256>>>(Wk,   wh + 1 * NW, wl + 1 * NW, NW);
    cvt_hilo<<<NW / 1024, 256>>>(Wv,   wh + 2 * NW, wl + 2 * NW, NW);
    cvt_hilo<<<NW / 1024, 256>>>(Wout, wh + 3 * NW, wl + 3 * NW, NW);

    dim3 ggrid(DMODEL / 128, MROWS / 128);   // (4, 128)
    gemm_hmma3<<<ggrid, 256, GEMM_SMEM>>>(xh, xl, wh + 0 * NW, wl + 0 * NW, gQ, nullptr);
    gemm_hmma3<<<ggrid, 256, GEMM_SMEM>>>(xh, xl, wh + 1 * NW, wl + 1 * NW, gK, nullptr);
    gemm_hmma3<<<ggrid, 256, GEMM_SMEM>>>(xh, xl, wh + 2 * NW, wl + 2 * NW, gV, nullptr);

    {
        int total_groups = 2 * MROWS * HEADS;
        int blocks = total_groups / 8;
        ln64_kernel<<<blocks, 256>>>(gQ, gK);
    }

    attn_kernel<<<MROWS, 256>>>(gQ, gK, gV, idx, ah, al);

    gemm_hmma3<<<ggrid, 256, GEMM_SMEM>>>(ah, al, wh + 3 * NW, wl + 3 * NW, out, bout);
}

// round 4
// speedup vs baseline: 2.0359x; 1.0964x over previous
#include <cuda_runtime.h>
#include <cuda_bf16.h>
#include <cstdint>

// Problem constants
#define BATCH 2
#define SEQN  8192
#define DMODEL 512
#define HEADS 8
#define DK 64
#define KNN 32
#define MROWS (BATCH*SEQN)   // 16384
#define LN_EPS 1e-5f

// ---------------- scratch (device globals; no allocation allowed) -------------
__device__ __align__(128) float g_Q[MROWS * DMODEL];
__device__ __align__(128) float g_K[MROWS * DMODEL];
__device__ __align__(128) float g_V[MROWS * DMODEL];
__device__ __align__(128) __nv_bfloat16 g_xh[MROWS * DMODEL];
__device__ __align__(128) __nv_bfloat16 g_xl[MROWS * DMODEL];
__device__ __align__(128) __nv_bfloat16 g_ah[MROWS * DMODEL];
__device__ __align__(128) __nv_bfloat16 g_al[MROWS * DMODEL];
__device__ __align__(128) __nv_bfloat16 g_Wh[4 * DMODEL * DMODEL];
__device__ __align__(128) __nv_bfloat16 g_Wl[4 * DMODEL * DMODEL];

// ---------------- small helpers -------------------------------------------------
__device__ __forceinline__ uint32_t smem_u32(const void* p) {
    uint32_t a;
    asm("{ .reg .u64 t; cvta.to.shared.u64 t, %1; cvt.u32.u64 %0, t; }"
        : "=r"(a) : "l"(p));
    return a;
}

__device__ __forceinline__ void ldsm_x4(uint32_t (&r)[4], uint32_t addr) {
    asm volatile("ldmatrix.sync.aligned.m8n8.x4.shared.b16 {%0,%1,%2,%3}, [%4];"
                 : "=r"(r[0]), "=r"(r[1]), "=r"(r[2]), "=r"(r[3]) : "r"(addr));
}

__device__ __forceinline__ void mma16816(float (&c)[4], const uint32_t (&a)[4],
                                         const uint32_t b0, const uint32_t b1) {
    asm volatile("mma.sync.aligned.m16n8k16.row.col.f32.bf16.bf16.f32 "
                 "{%0,%1,%2,%3}, {%4,%5,%6,%7}, {%8,%9}, {%0,%1,%2,%3};"
                 : "+f"(c[0]), "+f"(c[1]), "+f"(c[2]), "+f"(c[3])
                 : "r"(a[0]), "r"(a[1]), "r"(a[2]), "r"(a[3]), "r"(b0), "r"(b1));
}

__device__ __forceinline__ void cp16(uint32_t saddr, const void* gaddr) {
    asm volatile("cp.async.cg.shared.global [%0], [%1], 16;"
                 :: "r"(saddr), "l"(gaddr) : "memory");
}
#define CP_COMMIT() asm volatile("cp.async.commit_group;" ::: "memory")
#define CP_WAIT1()  asm volatile("cp.async.wait_group 1;" ::: "memory")
#define CP_WAIT0()  asm volatile("cp.async.wait_group 0;" ::: "memory")

// ---------------- tensor-core GEMM: C_t = A(16384x512) * W_t^T -----------------
// A, W as bf16 hi/lo splits; fp32 accum via 3 MMAs (hh + hl + lh).
// CTA tile 256(M) x 128(N), BK=32, 8 warps (4x2), warp tile 64x64, 2-stage cp.async.
// Multi-matrix: blockIdx.x selects (matrix t, col block) with 4 col blocks per matrix.
#define BKC 32
#define NCH (DMODEL / BKC)     // 16
#define PITCH 40               // bf16 elems per smem row (80B, conflict-free ldmatrix)
#define TILE_A_B (256 * PITCH * 2)      // 20480 B
#define TILE_B_B (128 * PITCH * 2)      // 10240 B
#define STAGE_B (2 * TILE_A_B + 2 * TILE_B_B)   // 61440 B
#define GEMM_SMEM (2 * STAGE_B)                 // 122880 B

__global__ __launch_bounds__(256, 1)
void gemm_hmma3(const __nv_bfloat16* __restrict__ Ah, const __nv_bfloat16* __restrict__ Al,
                const __nv_bfloat16* __restrict__ Wh, const __nv_bfloat16* __restrict__ Wl,
                float* __restrict__ C0, float* __restrict__ C1, float* __restrict__ C2,
                const float* __restrict__ bias)
{
    extern __shared__ char smem[];
    const uint32_t sbase = smem_u32(smem);
    const int tid  = threadIdx.x;
    const int wid  = tid >> 5;
    const int lane = tid & 31;

    const int tmat = blockIdx.x >> 2;              // which weight matrix / output
    const int bnn  = (blockIdx.x & 3) * 128;       // col block inside matrix
    const int bm   = blockIdx.y * 256;
    const int warp_m = wid & 3;                    // 0..3 (64 rows each)
    const int warp_n = wid >> 2;                   // 0..1 (64 cols each)

    const __nv_bfloat16* Bh = Wh + (size_t)tmat * DMODEL * DMODEL;
    const __nv_bfloat16* Bl = Wl + (size_t)tmat * DMODEL * DMODEL;
    float* C = (tmat == 0) ? C0 : (tmat == 1) ? C1 : C2;

    const int lr = tid >> 2;             // 0..63
    const int lc = tid & 3;              // 16B chunk

    auto load_stage = [&](int c, int buf) {
        const uint32_t s0 = sbase + buf * STAGE_B;
        const int kc = c * BKC;
        #pragma unroll
        for (int t = 0; t < 2; ++t) {
            const __nv_bfloat16* g = t ? Al : Ah;
            const uint32_t tb = s0 + t * TILE_A_B;
            #pragma unroll
            for (int p = 0; p < 4; ++p) {
                const int r = lr + p * 64;
                cp16(tb + (uint32_t)(r * (PITCH * 2) + lc * 16),
                     g + (size_t)(bm + r) * DMODEL + kc + lc * 8);
            }
        }
        #pragma unroll
        for (int t = 0; t < 2; ++t) {
            const __nv_bfloat16* g = t ? Bl : Bh;
            const uint32_t tb = s0 + 2 * TILE_A_B + t * TILE_B_B;
            #pragma unroll
            for (int p = 0; p < 2; ++p) {
                const int r = lr + p * 64;
                cp16(tb + (uint32_t)(r * (PITCH * 2) + lc * 16),
                     g + (size_t)(bnn + r) * DMODEL + kc + lc * 8);
            }
        }
        CP_COMMIT();
    };

    float acc[4][8][4];
    #pragma unroll
    for (int i = 0; i < 4; i++)
        #pragma unroll
        for (int j = 0; j < 8; j++)
            #pragma unroll
            for (int r = 0; r < 4; r++) acc[i][j][r] = 0.f;

    load_stage(0, 0);
    load_stage(1, 1);

    const int aRow  = lane & 15;
    const int aColB = (lane >> 4) * 8;
    const int quad  = lane >> 3;
    const int bRowL = (quad >> 1) * 8 + (lane & 7);
    const int bColB = (quad & 1) * 8;

    #pragma unroll 1
    for (int c = 0; c < NCH; ++c) {
        const int buf = c & 1;
        if (c + 1 < NCH) CP_WAIT1(); else CP_WAIT0();
        __syncthreads();

        const uint32_t sAh = sbase + buf * STAGE_B;
        const uint32_t sAl = sAh + TILE_A_B;
        const uint32_t sBh = sAh + 2 * TILE_A_B;
        const uint32_t sBl = sBh + TILE_B_B;

        #pragma unroll
        for (int ks = 0; ks < 2; ++ks) {
            uint32_t af[2][4][4];
            uint32_t bfr[2][8][2];
            #pragma unroll
            for (int i = 0; i < 4; ++i) {
                const uint32_t ao = (uint32_t)((warp_m * 64 + i * 16 + aRow) * PITCH
                                               + ks * 16 + aColB) * 2;
                ldsm_x4(af[0][i], sAh + ao);
                ldsm_x4(af[1][i], sAl + ao);
            }
            #pragma unroll
            for (int p = 0; p < 4; ++p) {
                const uint32_t bo = (uint32_t)((warp_n * 64 + p * 16 + bRowL) * PITCH
                                               + ks * 16 + bColB) * 2;
                uint32_t r0[4], r1[4];
                ldsm_x4(r0, sBh + bo);
                ldsm_x4(r1, sBl + bo);
                bfr[0][2*p][0]   = r0[0]; bfr[0][2*p][1]   = r0[1];
                bfr[0][2*p+1][0] = r0[2]; bfr[0][2*p+1][1] = r0[3];
                bfr[1][2*p][0]   = r1[0]; bfr[1][2*p][1]   = r1[1];
                bfr[1][2*p+1][0] = r1[2]; bfr[1][2*p+1][1] = r1[3];
            }
            #pragma unroll
            for (int i = 0; i < 4; ++i)
                #pragma unroll
                for (int j = 0; j < 8; ++j) {
                    mma16816(acc[i][j], af[0][i], bfr[0][j][0], bfr[0][j][1]);
                    mma16816(acc[i][j], af[0][i], bfr[1][j][0], bfr[1][j][1]);
                    mma16816(acc[i][j], af[1][i], bfr[0][j][0], bfr[0][j][1]);
                }
        }
        __syncthreads();
        if (c + 2 < NCH) load_stage(c + 2, buf);
    }

    // epilogue
    const int mBase = bm + warp_m * 64 + (lane >> 2);
    const int nBase = bnn + warp_n * 64 + (lane & 3) * 2;
    #pragma unroll
    for (int i = 0; i < 4; ++i) {
        #pragma unroll
        for (int j = 0; j < 8; ++j) {
            const int row = mBase + i * 16;
            const int col = nBase + j * 8;
            float2 v0 = make_float2(acc[i][j][0], acc[i][j][1]);
            float2 v1 = make_float2(acc[i][j][2], acc[i][j][3]);
            if (bias) {
                const float b0 = bias[col], b1 = bias[col + 1];
                v0.x += b0; v0.y += b1; v1.x += b0; v1.y += b1;
            }
            *(float2*)(C + (size_t)row * DMODEL + col)       = v0;
            *(float2*)(C + (size_t)(row + 8) * DMODEL + col) = v1;
        }
    }
}

// ---------------- fp32 -> bf16 hi/lo split --------------------------------------
__global__ void cvt_hilo(const float* __restrict__ s,
                         __nv_bfloat16* __restrict__ hi, __nv_bfloat16* __restrict__ lo,
                         int n)
{
    int i = (blockIdx.x * blockDim.x + threadIdx.x) * 4;
    if (i >= n) return;
    float4 v = *(const float4*)(s + i);
    __nv_bfloat16 h0 = __float2bfloat16(v.x);
    __nv_bfloat16 h1 = __float2bfloat16(v.y);
    __nv_bfloat16 h2 = __float2bfloat16(v.z);
    __nv_bfloat16 h3 = __float2bfloat16(v.w);
    __nv_bfloat16 l0 = __float2bfloat16(v.x - __bfloat162float(h0));
    __nv_bfloat16 l1 = __float2bfloat16(v.y - __bfloat162float(h1));
    __nv_bfloat16 l2 = __float2bfloat16(v.z - __bfloat162float(h2));
    __nv_bfloat16 l3 = __float2bfloat16(v.w - __bfloat162float(h3));
    __nv_bfloat162* hp = (__nv_bfloat162*)(hi + i);
    __nv_bfloat162* lp = (__nv_bfloat162*)(lo + i);
    hp[0] = __nv_bfloat162{h0, h1}; hp[1] = __nv_bfloat162{h2, h3};
    lp[0] = __nv_bfloat162{l0, l1}; lp[1] = __nv_bfloat162{l2, l3};
}

// ---------------- warp reduce helpers -----------------------------------------
__device__ __forceinline__ float warp_sum(float v) {
    v += __shfl_xor_sync(0xffffffffu, v, 16);
    v += __shfl_xor_sync(0xffffffffu, v, 8);
    v += __shfl_xor_sync(0xffffffffu, v, 4);
    v += __shfl_xor_sync(0xffffffffu, v, 2);
    v += __shfl_xor_sync(0xffffffffu, v, 1);
    return v;
}
__device__ __forceinline__ float warp_max(float v) {
    v = fmaxf(v, __shfl_xor_sync(0xffffffffu, v, 16));
    v = fmaxf(v, __shfl_xor_sync(0xffffffffu, v, 8));
    v = fmaxf(v, __shfl_xor_sync(0xffffffffu, v, 4));
    v = fmaxf(v, __shfl_xor_sync(0xffffffffu, v, 2));
    v = fmaxf(v, __shfl_xor_sync(0xffffffffu, v, 1));
    return v;
}

// ---------------- LayerNorm over 64-element groups (K only, in place) ----------
__global__ void ln64_kernel(float* __restrict__ Kt)
{
    const int warps_per_block = blockDim.x >> 5;
    int gid = blockIdx.x * warps_per_block + (threadIdx.x >> 5);
    const int lane = threadIdx.x & 31;
    float* base = Kt + (size_t)gid * DK;

    float v0 = base[lane];
    float v1 = base[lane + 32];
    float mean = warp_sum(v0 + v1) * (1.0f / 64.0f);
    float d0 = v0 - mean, d1 = v1 - mean;
    float var = warp_sum(d0 * d0 + d1 * d1) * (1.0f / 64.0f);
    float r = rsqrtf(var + LN_EPS);
    base[lane]      = d0 * r;
    base[lane + 32] = d1 * r;
}

// ---------------- fused gather-attention (Q-LN inline, bf16 hi/lo output) -------
__global__ __launch_bounds__(256)
void attn_kernel(const float* __restrict__ Q, const float* __restrict__ Kt,
                 const float* __restrict__ V, const int* __restrict__ idx,
                 __nv_bfloat16* __restrict__ oh, __nv_bfloat16* __restrict__ ol)
{
    __shared__ int srows[KNN];
    const int bn = blockIdx.x;
    const int b  = bn >> 13;
    const int n  = bn & (SEQN - 1);
    const int tid = threadIdx.x;
    if (tid < KNN) srows[tid] = idx[n * KNN + tid];
    __syncthreads();

    const int h    = tid >> 5;
    const int lane = tid & 31;
    const int qbase = bn * DMODEL + h * DK;
    float q0 = Q[qbase + lane];
    float q1 = Q[qbase + 32 + lane];
    // fused LayerNorm(q) and 1/sqrt(dk) scaling
    {
        const float mean = warp_sum(q0 + q1) * (1.0f / 64.0f);
        const float d0 = q0 - mean, d1 = q1 - mean;
        const float var = warp_sum(d0 * d0 + d1 * d1) * (1.0f / 64.0f);
        const float r = rsqrtf(var + LN_EPS) * 0.125f;
        q0 = d0 * r; q1 = d1 * r;
    }
    const int rowbase = b * SEQN;

    float s = 0.f;
    #pragma unroll 4
    for (int k = 0; k < KNN; ++k) {
        const int row = srows[k];
        const float* kp = Kt + (size_t)(rowbase + row) * DMODEL + h * DK;
        float p = fmaf(q0, kp[lane], q1 * kp[lane + 32]);
        p += __shfl_xor_sync(0xffffffffu, p, 16);
        p += __shfl_xor_sync(0xffffffffu, p, 8);
        p += __shfl_xor_sync(0xffffffffu, p, 4);
        p += __shfl_xor_sync(0xffffffffu, p, 2);
        p += __shfl_xor_sync(0xffffffffu, p, 1);
        if (lane == k) s = p;
    }

    const float m = warp_max(s);
    const float e = __expf(s - m);
    const float denom = warp_sum(e);
    const float a = e / denom;

    float o0 = 0.f, o1 = 0.f;
    #pragma unroll 4
    for (int k = 0; k < KNN; ++k) {
        const int row = srows[k];
        const float ak = __shfl_sync(0xffffffffu, a, k);
        const float* vp = V + (size_t)(rowbase + row) * DMODEL + h * DK;
        o0 = fmaf(ak, vp[lane],      o0);
        o1 = fmaf(ak, vp[lane + 32], o1);
    }
    __nv_bfloat16 h0 = __float2bfloat16(o0);
    __nv_bfloat16 h1 = __float2bfloat16(o1);
    oh[qbase + lane]      = h0;
    oh[qbase + 32 + lane] = h1;
    ol[qbase + lane]      = __float2bfloat16(o0 - __bfloat162float(h0));
    ol[qbase + 32 + lane] = __float2bfloat16(o1 - __bfloat162float(h1));
}

// ---------------- launch ---------------------------------------------------------
extern "C" void kernel_launch(void* const* d_in, const int* in_sizes, int n_in,
                              void* d_out, int out_size)
{
    const float* x    = (const float*)d_in[0];
    const int*   idx  = (const int*)  d_in[1];
    const float* Wq   = (const float*)d_in[2];
    const float* Wk   = (const float*)d_in[3];
    const float* Wv   = (const float*)d_in[4];
    const float* Wout = (const float*)d_in[5];
    const float* bout = (const float*)d_in[6];
    float* out = (float*)d_out;

    static float *gQ = nullptr, *gK = nullptr, *gV = nullptr;
    static __nv_bfloat16 *xh, *xl, *ah, *al, *wh, *wl;
    if (!gQ) {
        cudaGetSymbolAddress((void**)&gQ, g_Q);
        cudaGetSymbolAddress((void**)&gK, g_K);
        cudaGetSymbolAddress((void**)&gV, g_V);
        cudaGetSymbolAddress((void**)&xh, g_xh);
        cudaGetSymbolAddress((void**)&xl, g_xl);
        cudaGetSymbolAddress((void**)&ah, g_ah);
        cudaGetSymbolAddress((void**)&al, g_al);
        cudaGetSymbolAddress((void**)&wh, g_Wh);
        cudaGetSymbolAddress((void**)&wl, g_Wl);
        cudaFuncSetAttribute(gemm_hmma3, cudaFuncAttributeMaxDynamicSharedMemorySize,
                             GEMM_SMEM);
    }

    const int NX = MROWS * DMODEL;      // 8388608
    const int NW = DMODEL * DMODEL;     // 262144

    cvt_hilo<<<NX / 1024, 256>>>(x, xh, xl, NX);
    cvt_hilo<<<NW / 1024, 256>>>(Wq,   wh + 0 * NW, wl + 0 * NW, NW);
    cvt_hilo<<<NW / 1024, 256>>>(Wk,   wh + 1 * NW, wl + 1 * NW, NW);
    cvt_hilo<<<NW / 1024, 256>>>(Wv,   wh + 2 * NW, wl + 2 * NW, NW);
    cvt_hilo<<<NW / 1024, 256>>>(Wout, wh + 3 * NW, wl + 3 * NW, NW);

    // fused Q,K,V projections: 3 matrices x 4 col-blocks, 64 row-blocks
    gemm_hmma3<<<dim3(12, 64), 256, GEMM_SMEM>>>(xh, xl, wh, wl, gQ, gK, gV, nullptr);

    // LayerNorm on K only (Q's LN fused into attention)
    ln64_kernel<<<(MROWS * HEADS) / 8, 256>>>(gK);

    attn_kernel<<<MROWS, 256>>>(gQ, gK, gV, idx, ah, al);

    // output projection + bias
    gemm_hmma3<<<dim3(4, 64), 256, GEMM_SMEM>>>(ah, al, wh + 3 * NW, wl + 3 * NW,
                                                out, out, out, bout);
}

// round 5
// speedup vs baseline: 2.0581x; 1.0109x over previous
#include <cuda_runtime.h>
#include <cuda_bf16.h>
#include <cstdint>

// Problem constants
#define BATCH 2
#define SEQN  8192
#define DMODEL 512
#define HEADS 8
#define DK 64
#define KNN 32
#define MROWS (BATCH*SEQN)   // 16384
#define LN_EPS 1e-5f

// ---------------- scratch (device globals; no allocation allowed) -------------
__device__ __align__(128) float g_Q[MROWS * DMODEL];
__device__ __align__(128) float g_K[MROWS * DMODEL];
__device__ __align__(128) float g_V[MROWS * DMODEL];
__device__ __align__(128) __nv_bfloat16 g_xh[MROWS * DMODEL];
__device__ __align__(128) __nv_bfloat16 g_xl[MROWS * DMODEL];
__device__ __align__(128) __nv_bfloat16 g_ah[MROWS * DMODEL];
__device__ __align__(128) __nv_bfloat16 g_al[MROWS * DMODEL];
__device__ __align__(128) __nv_bfloat16 g_Wh[4 * DMODEL * DMODEL];
__device__ __align__(128) __nv_bfloat16 g_Wl[4 * DMODEL * DMODEL];

// ---------------- small helpers -------------------------------------------------
__device__ __forceinline__ uint32_t smem_u32(const void* p) {
    uint32_t a;
    asm("{ .reg .u64 t; cvta.to.shared.u64 t, %1; cvt.u32.u64 %0, t; }"
        : "=r"(a) : "l"(p));
    return a;
}

__device__ __forceinline__ void ldsm_x4(uint32_t (&r)[4], uint32_t addr) {
    asm volatile("ldmatrix.sync.aligned.m8n8.x4.shared.b16 {%0,%1,%2,%3}, [%4];"
                 : "=r"(r[0]), "=r"(r[1]), "=r"(r[2]), "=r"(r[3]) : "r"(addr));
}

__device__ __forceinline__ void mma16816(float (&c)[4], const uint32_t (&a)[4],
                                         const uint32_t b0, const uint32_t b1) {
    asm volatile("mma.sync.aligned.m16n8k16.row.col.f32.bf16.bf16.f32 "
                 "{%0,%1,%2,%3}, {%4,%5,%6,%7}, {%8,%9}, {%0,%1,%2,%3};"
                 : "+f"(c[0]), "+f"(c[1]), "+f"(c[2]), "+f"(c[3])
                 : "r"(a[0]), "r"(a[1]), "r"(a[2]), "r"(a[3]), "r"(b0), "r"(b1));
}

__device__ __forceinline__ void cp16(uint32_t saddr, const void* gaddr) {
    asm volatile("cp.async.cg.shared.global [%0], [%1], 16;"
                 :: "r"(saddr), "l"(gaddr) : "memory");
}
#define CP_COMMIT() asm volatile("cp.async.commit_group;" ::: "memory")
#define CP_WAIT1()  asm volatile("cp.async.wait_group 1;" ::: "memory")
#define CP_WAIT0()  asm volatile("cp.async.wait_group 0;" ::: "memory")

// ---------------- tensor-core GEMM: C_t = A(16384x512) * W_t^T -----------------
// A, W as bf16 hi/lo splits; fp32 accum via 3 MMAs (hh + hl + lh).
// CTA tile 256(M) x 128(N), BK=32, 8 warps (4x2), warp tile 64x64.
// 3-stage cp.async pipeline, one sync per chunk, loads 2 chunks ahead.
#define BKC 32
#define NCH (DMODEL / BKC)     // 16
#define PITCH 40               // bf16 elems per smem row (80B, conflict-free ldmatrix)
#define TILE_A_B (256 * PITCH * 2)      // 20480 B
#define TILE_B_B (128 * PITCH * 2)      // 10240 B
#define STAGE_B (2 * TILE_A_B + 2 * TILE_B_B)   // 61440 B
#define NSTAGE 3
#define GEMM_SMEM (NSTAGE * STAGE_B)            // 184320 B

__global__ __launch_bounds__(256, 1)
void gemm_hmma3(const __nv_bfloat16* __restrict__ Ah, const __nv_bfloat16* __restrict__ Al,
                const __nv_bfloat16* __restrict__ Wh, const __nv_bfloat16* __restrict__ Wl,
                float* __restrict__ C0, float* __restrict__ C1, float* __restrict__ C2,
                const float* __restrict__ bias)
{
    extern __shared__ char smem[];
    const uint32_t sbase = smem_u32(smem);
    const int tid  = threadIdx.x;
    const int wid  = tid >> 5;
    const int lane = tid & 31;

    const int tmat = blockIdx.x >> 2;              // which weight matrix / output
    const int bnn  = (blockIdx.x & 3) * 128;       // col block inside matrix
    const int bm   = blockIdx.y * 256;
    const int warp_m = wid & 3;                    // 0..3 (64 rows each)
    const int warp_n = wid >> 2;                   // 0..1 (64 cols each)

    const __nv_bfloat16* Bh = Wh + (size_t)tmat * DMODEL * DMODEL;
    const __nv_bfloat16* Bl = Wl + (size_t)tmat * DMODEL * DMODEL;
    float* C = (tmat == 0) ? C0 : (tmat == 1) ? C1 : C2;

    const int lr = tid >> 2;             // 0..63
    const int lc = tid & 3;              // 16B chunk

    auto load_stage = [&](int c, int buf) {
        const uint32_t s0 = sbase + buf * STAGE_B;
        const int kc = c * BKC;
        #pragma unroll
        for (int t = 0; t < 2; ++t) {
            const __nv_bfloat16* g = t ? Al : Ah;
            const uint32_t tb = s0 + t * TILE_A_B;
            #pragma unroll
            for (int p = 0; p < 4; ++p) {
                const int r = lr + p * 64;
                cp16(tb + (uint32_t)(r * (PITCH * 2) + lc * 16),
                     g + (size_t)(bm + r) * DMODEL + kc + lc * 8);
            }
        }
        #pragma unroll
        for (int t = 0; t < 2; ++t) {
            const __nv_bfloat16* g = t ? Bl : Bh;
            const uint32_t tb = s0 + 2 * TILE_A_B + t * TILE_B_B;
            #pragma unroll
            for (int p = 0; p < 2; ++p) {
                const int r = lr + p * 64;
                cp16(tb + (uint32_t)(r * (PITCH * 2) + lc * 16),
                     g + (size_t)(bnn + r) * DMODEL + kc + lc * 8);
            }
        }
        CP_COMMIT();
    };

    float acc[4][8][4];
    #pragma unroll
    for (int i = 0; i < 4; i++)
        #pragma unroll
        for (int j = 0; j < 8; j++)
            #pragma unroll
            for (int r = 0; r < 4; r++) acc[i][j][r] = 0.f;

    load_stage(0, 0);
    load_stage(1, 1);

    const int aRow  = lane & 15;
    const int aColB = (lane >> 4) * 8;
    const int quad  = lane >> 3;
    const int bRowL = (quad >> 1) * 8 + (lane & 7);
    const int bColB = (quad & 1) * 8;

    #pragma unroll 1
    for (int c = 0; c < NCH; ++c) {
        const int buf = c % NSTAGE;
        if (c + 1 < NCH) CP_WAIT1(); else CP_WAIT0();
        __syncthreads();
        // prefetch chunk c+2 into buffer (c+2)%3 (not touched by compute of c)
        if (c + 2 < NCH) load_stage(c + 2, (c + 2) % NSTAGE);

        const uint32_t sAh = sbase + buf * STAGE_B;
        const uint32_t sAl = sAh + TILE_A_B;
        const uint32_t sBh = sAh + 2 * TILE_A_B;
        const uint32_t sBl = sBh + TILE_B_B;

        #pragma unroll
        for (int ks = 0; ks < 2; ++ks) {
            uint32_t af[2][4][4];
            uint32_t bfr[2][8][2];
            #pragma unroll
            for (int i = 0; i < 4; ++i) {
                const uint32_t ao = (uint32_t)((warp_m * 64 + i * 16 + aRow) * PITCH
                                               + ks * 16 + aColB) * 2;
                ldsm_x4(af[0][i], sAh + ao);
                ldsm_x4(af[1][i], sAl + ao);
            }
            #pragma unroll
            for (int p = 0; p < 4; ++p) {
                const uint32_t bo = (uint32_t)((warp_n * 64 + p * 16 + bRowL) * PITCH
                                               + ks * 16 + bColB) * 2;
                uint32_t r0[4], r1[4];
                ldsm_x4(r0, sBh + bo);
                ldsm_x4(r1, sBl + bo);
                bfr[0][2*p][0]   = r0[0]; bfr[0][2*p][1]   = r0[1];
                bfr[0][2*p+1][0] = r0[2]; bfr[0][2*p+1][1] = r0[3];
                bfr[1][2*p][0]   = r1[0]; bfr[1][2*p][1]   = r1[1];
                bfr[1][2*p+1][0] = r1[2]; bfr[1][2*p+1][1] = r1[3];
            }
            // split-term loop outermost: 32 independent MMAs between acc reuse
            #pragma unroll
            for (int t = 0; t < 3; ++t) {
                const int ai = (t == 2) ? 1 : 0;
                const int bi = (t == 1) ? 1 : 0;
                #pragma unroll
                for (int i = 0; i < 4; ++i)
                    #pragma unroll
                    for (int j = 0; j < 8; ++j)
                        mma16816(acc[i][j], af[ai][i], bfr[bi][j][0], bfr[bi][j][1]);
            }
        }
    }

    // epilogue
    const int mBase = bm + warp_m * 64 + (lane >> 2);
    const int nBase = bnn + warp_n * 64 + (lane & 3) * 2;
    #pragma unroll
    for (int i = 0; i < 4; ++i) {
        #pragma unroll
        for (int j = 0; j < 8; ++j) {
            const int row = mBase + i * 16;
            const int col = nBase + j * 8;
            float2 v0 = make_float2(acc[i][j][0], acc[i][j][1]);
            float2 v1 = make_float2(acc[i][j][2], acc[i][j][3]);
            if (bias) {
                const float b0 = bias[col], b1 = bias[col + 1];
                v0.x += b0; v0.y += b1; v1.x += b0; v1.y += b1;
            }
            *(float2*)(C + (size_t)row * DMODEL + col)       = v0;
            *(float2*)(C + (size_t)(row + 8) * DMODEL + col) = v1;
        }
    }
}

// ---------------- fp32 -> bf16 hi/lo split --------------------------------------
__global__ void cvt_hilo(const float* __restrict__ s,
                         __nv_bfloat16* __restrict__ hi, __nv_bfloat16* __restrict__ lo,
                         int n)
{
    int i = (blockIdx.x * blockDim.x + threadIdx.x) * 4;
    if (i >= n) return;
    float4 v = *(const float4*)(s + i);
    __nv_bfloat16 h0 = __float2bfloat16(v.x);
    __nv_bfloat16 h1 = __float2bfloat16(v.y);
    __nv_bfloat16 h2 = __float2bfloat16(v.z);
    __nv_bfloat16 h3 = __float2bfloat16(v.w);
    __nv_bfloat16 l0 = __float2bfloat16(v.x - __bfloat162float(h0));
    __nv_bfloat16 l1 = __float2bfloat16(v.y - __bfloat162float(h1));
    __nv_bfloat16 l2 = __float2bfloat16(v.z - __bfloat162float(h2));
    __nv_bfloat16 l3 = __float2bfloat16(v.w - __bfloat162float(h3));
    __nv_bfloat162* hp = (__nv_bfloat162*)(hi + i);
    __nv_bfloat162* lp = (__nv_bfloat162*)(lo + i);
    hp[0] = __nv_bfloat162{h0, h1}; hp[1] = __nv_bfloat162{h2, h3};
    lp[0] = __nv_bfloat162{l0, l1}; lp[1] = __nv_bfloat162{l2, l3};
}

// ---------------- warp reduce helpers -----------------------------------------
__device__ __forceinline__ float warp_sum(float v) {
    v += __shfl_xor_sync(0xffffffffu, v, 16);
    v += __shfl_xor_sync(0xffffffffu, v, 8);
    v += __shfl_xor_sync(0xffffffffu, v, 4);
    v += __shfl_xor_sync(0xffffffffu, v, 2);
    v += __shfl_xor_sync(0xffffffffu, v, 1);
    return v;
}
__device__ __forceinline__ float warp_max(float v) {
    v = fmaxf(v, __shfl_xor_sync(0xffffffffu, v, 16));
    v = fmaxf(v, __shfl_xor_sync(0xffffffffu, v, 8));
    v = fmaxf(v, __shfl_xor_sync(0xffffffffu, v, 4));
    v = fmaxf(v, __shfl_xor_sync(0xffffffffu, v, 2));
    v = fmaxf(v, __shfl_xor_sync(0xffffffffu, v, 1));
    return v;
}

// ---------------- LayerNorm over 64-element groups (K only, in place) ----------
__global__ void ln64_kernel(float* __restrict__ Kt)
{
    const int warps_per_block = blockDim.x >> 5;
    int gid = blockIdx.x * warps_per_block + (threadIdx.x >> 5);
    const int lane = threadIdx.x & 31;
    float* base = Kt + (size_t)gid * DK;

    float v0 = base[lane];
    float v1 = base[lane + 32];
    float mean = warp_sum(v0 + v1) * (1.0f / 64.0f);
    float d0 = v0 - mean, d1 = v1 - mean;
    float var = warp_sum(d0 * d0 + d1 * d1) * (1.0f / 64.0f);
    float r = rsqrtf(var + LN_EPS);
    base[lane]      = d0 * r;
    base[lane + 32] = d1 * r;
}

// ---------------- fused gather-attention (Q-LN inline, bf16 hi/lo output) -------
__global__ __launch_bounds__(256)
void attn_kernel(const float* __restrict__ Q, const float* __restrict__ Kt,
                 const float* __restrict__ V, const int* __restrict__ idx,
                 __nv_bfloat16* __restrict__ oh, __nv_bfloat16* __restrict__ ol)
{
    __shared__ int srows[KNN];
    const int bn = blockIdx.x;
    const int b  = bn >> 13;
    const int n  = bn & (SEQN - 1);
    const int tid = threadIdx.x;
    if (tid < KNN) srows[tid] = idx[n * KNN + tid];
    __syncthreads();

    const int h    = tid >> 5;
    const int lane = tid & 31;
    const int qbase = bn * DMODEL + h * DK;
    float q0 = Q[qbase + lane];
    float q1 = Q[qbase + 32 + lane];
    // fused LayerNorm(q) and 1/sqrt(dk) scaling
    {
        const float mean = warp_sum(q0 + q1) * (1.0f / 64.0f);
        const float d0 = q0 - mean, d1 = q1 - mean;
        const float var = warp_sum(d0 * d0 + d1 * d1) * (1.0f / 64.0f);
        const float r = rsqrtf(var + LN_EPS) * 0.125f;
        q0 = d0 * r; q1 = d1 * r;
    }
    const int rowbase = b * SEQN;

    float s = 0.f;
    #pragma unroll 4
    for (int k = 0; k < KNN; ++k) {
        const int row = srows[k];
        const float* kp = Kt + (size_t)(rowbase + row) * DMODEL + h * DK;
        float p = fmaf(q0, kp[lane], q1 * kp[lane + 32]);
        p += __shfl_xor_sync(0xffffffffu, p, 16);
        p += __shfl_xor_sync(0xffffffffu, p, 8);
        p += __shfl_xor_sync(0xffffffffu, p, 4);
        p += __shfl_xor_sync(0xffffffffu, p, 2);
        p += __shfl_xor_sync(0xffffffffu, p, 1);
        if (lane == k) s = p;
    }

    const float m = warp_max(s);
    const float e = __expf(s - m);
    const float denom = warp_sum(e);
    const float a = e / denom;

    float o0 = 0.f, o1 = 0.f;
    #pragma unroll 4
    for (int k = 0; k < KNN; ++k) {
        const int row = srows[k];
        const float ak = __shfl_sync(0xffffffffu, a, k);
        const float* vp = V + (size_t)(rowbase + row) * DMODEL + h * DK;
        o0 = fmaf(ak, vp[lane],      o0);
        o1 = fmaf(ak, vp[lane + 32], o1);
    }
    __nv_bfloat16 h0 = __float2bfloat16(o0);
    __nv_bfloat16 h1 = __float2bfloat16(o1);
    oh[qbase + lane]      = h0;
    oh[qbase + 32 + lane] = h1;
    ol[qbase + lane]      = __float2bfloat16(o0 - __bfloat162float(h0));
    ol[qbase + 32 + lane] = __float2bfloat16(o1 - __bfloat162float(h1));
}

// ---------------- launch ---------------------------------------------------------
extern "C" void kernel_launch(void* const* d_in, const int* in_sizes, int n_in,
                              void* d_out, int out_size)
{
    const float* x    = (const float*)d_in[0];
    const int*   idx  = (const int*)  d_in[1];
    const float* Wq   = (const float*)d_in[2];
    const float* Wk   = (const float*)d_in[3];
    const float* Wv   = (const float*)d_in[4];
    const float* Wout = (const float*)d_in[5];
    const float* bout = (const float*)d_in[6];
    float* out = (float*)d_out;

    static float *gQ = nullptr, *gK = nullptr, *gV = nullptr;
    static __nv_bfloat16 *xh, *xl, *ah, *al, *wh, *wl;
    if (!gQ) {
        cudaGetSymbolAddress((void**)&gQ, g_Q);
        cudaGetSymbolAddress((void**)&gK, g_K);
        cudaGetSymbolAddress((void**)&gV, g_V);
        cudaGetSymbolAddress((void**)&xh, g_xh);
        cudaGetSymbolAddress((void**)&xl, g_xl);
        cudaGetSymbolAddress((void**)&ah, g_ah);
        cudaGetSymbolAddress((void**)&al, g_al);
        cudaGetSymbolAddress((void**)&wh, g_Wh);
        cudaGetSymbolAddress((void**)&wl, g_Wl);
        cudaFuncSetAttribute(gemm_hmma3, cudaFuncAttributeMaxDynamicSharedMemorySize,
                             GEMM_SMEM);
    }

    const int NX = MROWS * DMODEL;      // 8388608
    const int NW = DMODEL * DMODEL;     // 262144

    cvt_hilo<<<NX / 1024, 256>>>(x, xh, xl, NX);
    cvt_hilo<<<NW / 1024, 256>>>(Wq,   wh + 0 * NW, wl + 0 * NW, NW);
    cvt_hilo<<<NW / 1024, 256>>>(Wk,   wh + 1 * NW, wl + 1 * NW, NW);
    cvt_hilo<<<NW / 1024, 256>>>(Wv,   wh + 2 * NW, wl + 2 * NW, NW);
    cvt_hilo<<<NW / 1024, 256>>>(Wout, wh + 3 * NW, wl + 3 * NW, NW);

    // fused Q,K,V projections: 3 matrices x 4 col-blocks, 64 row-blocks
    gemm_hmma3<<<dim3(12, 64), 256, GEMM_SMEM>>>(xh, xl, wh, wl, gQ, gK, gV, nullptr);

    // LayerNorm on K only (Q's LN fused into attention)
    ln64_kernel<<<(MROWS * HEADS) / 8, 256>>>(gK);

    attn_kernel<<<MROWS, 256>>>(gQ, gK, gV, idx, ah, al);

    // output projection + bias
    gemm_hmma3<<<dim3(4, 64), 256, GEMM_SMEM>>>(ah, al, wh + 3 * NW, wl + 3 * NW,
                                                out, out, out, bout);
}